// round 2
// baseline (speedup 1.0000x reference)
#include <cuda_runtime.h>
#include <math.h>

// Problem constants: B=4, S=1024, D=1024, H=16, DK=64
#define SEQ   1024
#define BATCH 4
#define DIM   1024
#define HEADS 16
#define DKH   64
#define MROWS (BATCH * SEQ)   // 4096

// ---------------- scratch (static device allocations) ----------------
__device__ float g_buf[MROWS * DIM];     // g = X @ W_G + b_G        (16 MB)
__device__ float kw_buf[MROWS * DIM];    // RoPE'd k, [b][s][h][dk]  (16 MB)
__device__ float q0_buf[BATCH * DIM];    // q at position 0
__device__ float row0_buf[BATCH * HEADS * SEQ];  // softmax rows
__device__ float cos_tab[SEQ * 32];
__device__ float sin_tab[SEQ * 32];

// ---------------- RoPE tables (match jnp fp32 formula) ----------------
__global__ void rope_tables_kernel() {
    int s = blockIdx.x;
    int j = threadIdx.x;                 // 0..31 (dk/2)
    float inv = powf(10000.0f, -((float)j) / 32.0f);   // 10000^(-2j/64)
    float ang = (float)s * inv;
    cos_tab[s * 32 + j] = cosf(ang);
    sin_tab[s * 32 + j] = sinf(ang);
}

// ---------------- 128x128x8 register-blocked SGEMM ----------------
// C[M=4096, N=1024] = A[M,1024] @ W[1024,1024] + bias ; PHASE1 fuses RoPE
template <int PHASE>
__global__ __launch_bounds__(256) void sgemm_kernel(
    const float* __restrict__ Aext,
    const float* __restrict__ W,
    const float* __restrict__ bias)
{
    const int K = DIM, N = DIM;
    const int BM = 128, BN = 128, BK = 8, TM = 8, TN = 8;

    const float* A = (PHASE == 0) ? Aext : g_buf;
    float*       C = (PHASE == 0) ? g_buf : kw_buf;

    __shared__ float As[BK][BM];
    __shared__ float Bs[BK][BN];

    int tid = threadIdx.x;
    int tx = tid % 16;          // 16 x 16 thread grid
    int ty = tid / 16;
    int brow = blockIdx.y * BM;
    int bcol = blockIdx.x * BN;

    // tile-load coordinates
    int arow   = tid >> 1;            // 0..127
    int acol   = (tid & 1) * 4;       // 0 or 4
    int brow_l = tid >> 5;            // 0..7
    int bcol_l = (tid & 31) * 4;      // 0..124

    const float* Ap = A + (brow + arow) * K + acol;
    const float* Bp = W + brow_l * N + bcol + bcol_l;

    float acc[TM][TN];
    #pragma unroll
    for (int i = 0; i < TM; i++)
        #pragma unroll
        for (int j = 0; j < TN; j++) acc[i][j] = 0.f;

    float ar[TM], br[TN];

    for (int kt = 0; kt < K; kt += BK) {
        float4 av = *(const float4*)(Ap + kt);
        float4 bv = *(const float4*)(Bp + kt * N);
        As[acol + 0][arow] = av.x;
        As[acol + 1][arow] = av.y;
        As[acol + 2][arow] = av.z;
        As[acol + 3][arow] = av.w;
        *(float4*)&Bs[brow_l][bcol_l] = bv;
        __syncthreads();

        #pragma unroll
        for (int kk = 0; kk < BK; kk++) {
            #pragma unroll
            for (int i = 0; i < TM; i += 4) {
                float4 v = *(const float4*)&As[kk][ty * TM + i];
                ar[i] = v.x; ar[i+1] = v.y; ar[i+2] = v.z; ar[i+3] = v.w;
            }
            #pragma unroll
            for (int j = 0; j < TN; j += 4) {
                float4 v = *(const float4*)&Bs[kk][tx * TN + j];
                br[j] = v.x; br[j+1] = v.y; br[j+2] = v.z; br[j+3] = v.w;
            }
            #pragma unroll
            for (int i = 0; i < TM; i++)
                #pragma unroll
                for (int j = 0; j < TN; j++)
                    acc[i][j] += ar[i] * br[j];
        }
        __syncthreads();
    }

    // ---- epilogue ----
    #pragma unroll
    for (int i = 0; i < TM; i++) {
        int row = brow + ty * TM + i;
        int col0 = bcol + tx * TN;
        if (PHASE == 1) {
            int s = row & (SEQ - 1);
            #pragma unroll
            for (int j = 0; j < TN; j += 2) {
                int col = col0 + j;
                float v0 = acc[i][j]     + bias[col];
                float v1 = acc[i][j + 1] + bias[col + 1];
                int jj = (col & (DKH - 1)) >> 1;
                float c  = cos_tab[s * 32 + jj];
                float sn = sin_tab[s * 32 + jj];
                C[row * N + col]     = v0 * c - v1 * sn;
                C[row * N + col + 1] = v1 * c + v0 * sn;
            }
        } else {
            #pragma unroll
            for (int j = 0; j < TN; j++) {
                int col = col0 + j;
                C[row * N + col] = acc[i][j] + bias[col];
            }
        }
    }
}

// ---------------- q0 = g[b, 0, :] @ Wq + bq  (RoPE@pos0 = identity) ----------------
__global__ __launch_bounds__(256) void q0_kernel(const float* __restrict__ Wq,
                                                 const float* __restrict__ bq)
{
    __shared__ float gs[DIM];
    int b = blockIdx.y;
    int c = blockIdx.x * 256 + threadIdx.x;
    const float* grow = g_buf + b * SEQ * DIM;   // row s=0 of batch b
    for (int i = threadIdx.x; i < DIM; i += 256) gs[i] = grow[i];
    __syncthreads();

    float a0 = 0.f, a1 = 0.f, a2 = 0.f, a3 = 0.f;
    #pragma unroll 4
    for (int k = 0; k < DIM; k += 4) {
        a0 += gs[k]     * Wq[(k)     * DIM + c];
        a1 += gs[k + 1] * Wq[(k + 1) * DIM + c];
        a2 += gs[k + 2] * Wq[(k + 2) * DIM + c];
        a3 += gs[k + 3] * Wq[(k + 3) * DIM + c];
    }
    q0_buf[b * DIM + c] = (a0 + a1) + (a2 + a3) + bq[c];
}

// ---------------- scores + softmax for query position 0 ----------------
__global__ __launch_bounds__(256) void attn_kernel(const int* __restrict__ mask)
{
    int bh = blockIdx.x;
    int b = bh >> 4, h = bh & 15;
    __shared__ float q0s[DKH];
    __shared__ float sc[SEQ];
    __shared__ float red[256];

    int tid = threadIdx.x;
    if (tid < DKH) q0s[tid] = q0_buf[b * DIM + h * DKH + tid];
    __syncthreads();

    int lane = tid & 31, warp = tid >> 5;
    const float scale = 0.125f;   // 1/sqrt(64)

    for (int s = warp; s < SEQ; s += 8) {
        const float* kr = kw_buf + (b * SEQ + s) * DIM + h * DKH;
        float v = q0s[lane] * kr[lane] + q0s[lane + 32] * kr[lane + 32];
        #pragma unroll
        for (int o = 16; o; o >>= 1) v += __shfl_down_sync(0xffffffffu, v, o);
        if (lane == 0) {
            float sv = v * scale;
            if (mask[b * SEQ + s] == 0) sv = -1e9f;
            sc[s] = sv;
        }
    }
    __syncthreads();

    // block softmax over 1024
    float m = -1e30f;
    for (int i = tid; i < SEQ; i += 256) m = fmaxf(m, sc[i]);
    red[tid] = m; __syncthreads();
    for (int o = 128; o; o >>= 1) {
        if (tid < o) red[tid] = fmaxf(red[tid], red[tid + o]);
        __syncthreads();
    }
    m = red[0];
    __syncthreads();

    float sum = 0.f;
    for (int i = tid; i < SEQ; i += 256) {
        float e = expf(sc[i] - m);
        sc[i] = e;
        sum += e;
    }
    red[tid] = sum; __syncthreads();
    for (int o = 128; o; o >>= 1) {
        if (tid < o) red[tid] += red[tid + o];
        __syncthreads();
    }
    float inv = 1.0f / red[0];
    for (int i = tid; i < SEQ; i += 256)
        row0_buf[bh * SEQ + i] = sc[i] * inv;
}

// ---------------- conv1d(k=3, 16->1024) + bias + relu ----------------
// grid: (S/512, D/64, B); thread owns 2 adjacent s, loops 64 output channels
__global__ __launch_bounds__(256) void conv_kernel(const float* __restrict__ conv_w,
                                                   const float* __restrict__ conv_b,
                                                   float* __restrict__ out)
{
    int b  = blockIdx.z;
    int o0 = blockIdx.y * 64;
    int s0 = blockIdx.x * 512;

    __shared__ float ws[64 * 48];
    __shared__ float bs[64];
    int tid = threadIdx.x;
    for (int idx = tid; idx < 64 * 48; idx += 256)
        ws[idx] = conv_w[o0 * 48 + idx];
    if (tid < 64) bs[tid] = conv_b[o0 + tid];
    __syncthreads();

    int s = s0 + tid * 2;                 // s in [0, 1022], even

    float r[16][4];
    #pragma unroll
    for (int i = 0; i < 16; i++) {
        const float* rp = row0_buf + (b * HEADS + i) * SEQ;
        r[i][0] = (s == 0) ? 0.f : rp[s - 1];
        r[i][1] = rp[s];
        r[i][2] = rp[s + 1];
        r[i][3] = (s + 2 > SEQ - 1) ? 0.f : rp[s + 2];
    }

    for (int o = 0; o < 64; o++) {
        float a0 = bs[o], a1 = bs[o];
        const float* w = &ws[o * 48];
        #pragma unroll
        for (int i = 0; i < 16; i++) {
            float w0 = w[i * 3], w1 = w[i * 3 + 1], w2 = w[i * 3 + 2];
            a0 += r[i][0] * w0 + r[i][1] * w1 + r[i][2] * w2;
            a1 += r[i][1] * w0 + r[i][2] * w1 + r[i][3] * w2;
        }
        float2 v = make_float2(fmaxf(a0, 0.f), fmaxf(a1, 0.f));
        *(float2*)&out[((b * DIM) + (o0 + o)) * SEQ + s] = v;
    }
}

// ---------------- launch ----------------
extern "C" void kernel_launch(void* const* d_in, const int* in_sizes, int n_in,
                              void* d_out, int out_size)
{
    const float* X      = (const float*)d_in[0];
    const int*   mask   = (const int*)  d_in[1];
    const float* W_G    = (const float*)d_in[2];
    const float* b_G    = (const float*)d_in[3];
    const float* Wq     = (const float*)d_in[4];
    const float* bq     = (const float*)d_in[5];
    const float* Wk     = (const float*)d_in[6];
    const float* bk     = (const float*)d_in[7];
    const float* conv_w = (const float*)d_in[8];
    const float* conv_b = (const float*)d_in[9];
    float* out = (float*)d_out;

    rope_tables_kernel<<<SEQ, 32>>>();
    sgemm_kernel<0><<<dim3(DIM / 128, MROWS / 128), 256>>>(X, W_G, b_G);       // g
    sgemm_kernel<1><<<dim3(DIM / 128, MROWS / 128), 256>>>(nullptr, Wk, bk);   // kw (+RoPE)
    q0_kernel<<<dim3(4, BATCH), 256>>>(Wq, bq);
    attn_kernel<<<BATCH * HEADS, 256>>>(mask);
    conv_kernel<<<dim3(SEQ / 512, DIM / 64, BATCH), 256>>>(conv_w, conv_b, out);
}

// round 6
// speedup vs baseline: 1.0918x; 1.0918x over previous
#include <cuda_runtime.h>
#include <math.h>

// Problem constants: B=4, S=1024, D=1024, H=16, DK=64
#define SEQ   1024
#define BATCH 4
#define DIM   1024
#define HEADS 16
#define DKH   64
#define MROWS (BATCH * SEQ)   // 4096

// ---------------- scratch (static device allocations) ----------------
__device__ float g_buf[MROWS * DIM];     // g = X @ W_G + b_G        (16 MB)
__device__ float kw_buf[MROWS * DIM];    // RoPE'd k, [b][s][h][dk]  (16 MB)
__device__ float g0_buf[BATCH * DIM];    // g rows at s==0 (extracted in epilogue)
__device__ float q0_part[8 * BATCH * DIM];
__device__ float q0_buf[BATCH * DIM];    // q at position 0
__device__ float sc_buf[BATCH * HEADS * SEQ];
__device__ float row0_buf[BATCH * HEADS * SEQ];  // softmax rows
__device__ float cos_tab[SEQ * 32];
__device__ float sin_tab[SEQ * 32];

// ---------------- RoPE tables (match jnp fp32 formula) ----------------
__global__ void rope_tables_kernel() {
    int s = blockIdx.x;
    int j = threadIdx.x;                 // 0..31 (dk/2)
    float inv = powf(10000.0f, -((float)j) / 32.0f);   // 10000^(-2j/64)
    float ang = (float)s * inv;
    cos_tab[s * 32 + j] = cosf(ang);
    sin_tab[s * 32 + j] = sinf(ang);
}

// ---------------- 128x128x8 register-blocked SGEMM (R2-proven) ----------------
// C[M=4096, N=1024] = A[M,1024] @ W[1024,1024] + bias ; PHASE1 fuses RoPE
template <int PHASE>
__global__ __launch_bounds__(256) void sgemm_kernel(
    const float* __restrict__ Aext,
    const float* __restrict__ W,
    const float* __restrict__ bias)
{
    const int K = DIM, N = DIM;
    const int BM = 128, BN = 128, BK = 8, TM = 8, TN = 8;

    const float* A = (PHASE == 0) ? Aext : g_buf;
    float*       C = (PHASE == 0) ? g_buf : kw_buf;

    __shared__ float As[BK][BM];
    __shared__ float Bs[BK][BN];

    int tid = threadIdx.x;
    int tx = tid % 16;          // 16 x 16 thread grid
    int ty = tid / 16;
    int brow = blockIdx.y * BM;
    int bcol = blockIdx.x * BN;

    // tile-load coordinates
    int arow   = tid >> 1;            // 0..127
    int acol   = (tid & 1) * 4;       // 0 or 4
    int brow_l = tid >> 5;            // 0..7
    int bcol_l = (tid & 31) * 4;      // 0..124

    const float* Ap = A + (brow + arow) * K + acol;
    const float* Bp = W + brow_l * N + bcol + bcol_l;

    float acc[TM][TN];
    #pragma unroll
    for (int i = 0; i < TM; i++)
        #pragma unroll
        for (int j = 0; j < TN; j++) acc[i][j] = 0.f;

    float ar[TM], br[TN];

    for (int kt = 0; kt < K; kt += BK) {
        float4 av = *(const float4*)(Ap + kt);
        float4 bv = *(const float4*)(Bp + kt * N);
        As[acol + 0][arow] = av.x;
        As[acol + 1][arow] = av.y;
        As[acol + 2][arow] = av.z;
        As[acol + 3][arow] = av.w;
        *(float4*)&Bs[brow_l][bcol_l] = bv;
        __syncthreads();

        #pragma unroll
        for (int kk = 0; kk < BK; kk++) {
            #pragma unroll
            for (int i = 0; i < TM; i += 4) {
                float4 v = *(const float4*)&As[kk][ty * TM + i];
                ar[i] = v.x; ar[i+1] = v.y; ar[i+2] = v.z; ar[i+3] = v.w;
            }
            #pragma unroll
            for (int j = 0; j < TN; j += 4) {
                float4 v = *(const float4*)&Bs[kk][tx * TN + j];
                br[j] = v.x; br[j+1] = v.y; br[j+2] = v.z; br[j+3] = v.w;
            }
            #pragma unroll
            for (int i = 0; i < TM; i++)
                #pragma unroll
                for (int j = 0; j < TN; j++)
                    acc[i][j] += ar[i] * br[j];
        }
        __syncthreads();
    }

    // ---- epilogue ----
    #pragma unroll
    for (int i = 0; i < TM; i++) {
        int row = brow + ty * TM + i;
        int col0 = bcol + tx * TN;
        if (PHASE == 1) {
            int s = row & (SEQ - 1);
            #pragma unroll
            for (int j = 0; j < TN; j += 2) {
                int col = col0 + j;
                float v0 = acc[i][j]     + bias[col];
                float v1 = acc[i][j + 1] + bias[col + 1];
                int jj = (col & (DKH - 1)) >> 1;
                float c  = cos_tab[s * 32 + jj];
                float sn = sin_tab[s * 32 + jj];
                C[row * N + col]     = v0 * c - v1 * sn;
                C[row * N + col + 1] = v1 * c + v0 * sn;
            }
        } else {
            #pragma unroll
            for (int j = 0; j < TN; j++) {
                int col = col0 + j;
                float v = acc[i][j] + bias[col];
                C[row * N + col] = v;
                if ((row & (SEQ - 1)) == 0)            // s == 0 rows -> g0
                    g0_buf[(row >> 10) * DIM + col] = v;
            }
        }
    }
}

// ============ q0 = g0 @ Wq (split-K partials), fp32 ============
__global__ __launch_bounds__(256) void q0_part_kernel(const float* __restrict__ Wq)
{
    __shared__ float gs[128];
    int b = blockIdx.z, ks = blockIdx.y, cb = blockIdx.x;
    int col = cb * 256 + threadIdx.x;
    if (threadIdx.x < 128) gs[threadIdx.x] = g0_buf[b * DIM + ks * 128 + threadIdx.x];
    __syncthreads();
    float a = 0.f;
    #pragma unroll 8
    for (int i = 0; i < 128; i++)
        a += gs[i] * Wq[(size_t)(ks * 128 + i) * DIM + col];
    q0_part[(ks * BATCH + b) * DIM + col] = a;
}
__global__ __launch_bounds__(256) void q0_reduce_kernel(const float* __restrict__ bq)
{
    int idx = blockIdx.x * 256 + threadIdx.x;    // 0..4095
    int b = idx >> 10, col = idx & (DIM - 1);
    float a = bq[col];
    #pragma unroll
    for (int ks = 0; ks < 8; ks++) a += q0_part[(ks * BATCH + b) * DIM + col];
    q0_buf[idx] = a;
}

// ============ scores (parallel over 512 CTAs) ============
__global__ __launch_bounds__(256) void scores_kernel(const int* __restrict__ mask)
{
    int bh = blockIdx.y, seg = blockIdx.x;
    int b = bh >> 4, h = bh & 15;
    __shared__ float q0s[DKH];
    int tid = threadIdx.x;
    if (tid < DKH) q0s[tid] = q0_buf[b * DIM + h * DKH + tid];
    __syncthreads();
    int lane = tid & 31, warp = tid >> 5;
    #pragma unroll 4
    for (int i = 0; i < 16; i++) {
        int s = seg * 128 + i * 8 + warp;
        const float* kr = kw_buf + ((size_t)(b * SEQ + s)) * DIM + h * DKH;
        float v = q0s[lane] * kr[lane] + q0s[lane + 32] * kr[lane + 32];
        #pragma unroll
        for (int o = 16; o; o >>= 1) v += __shfl_down_sync(0xffffffffu, v, o);
        if (lane == 0) {
            float sv = v * 0.125f;   // 1/sqrt(64)
            if (mask[b * SEQ + s] == 0) sv = -1e9f;
            sc_buf[bh * SEQ + s] = sv;
        }
    }
}

// ============ softmax over 1024 ============
__global__ __launch_bounds__(256) void softmax_kernel()
{
    int bh = blockIdx.x;
    __shared__ float sc[SEQ];
    __shared__ float red[256];
    int tid = threadIdx.x;
    float m = -1e30f;
    for (int i = tid; i < SEQ; i += 256) { float v = sc_buf[bh * SEQ + i]; sc[i] = v; m = fmaxf(m, v); }
    red[tid] = m; __syncthreads();
    for (int o = 128; o; o >>= 1) { if (tid < o) red[tid] = fmaxf(red[tid], red[tid + o]); __syncthreads(); }
    m = red[0]; __syncthreads();
    float sum = 0.f;
    for (int i = tid; i < SEQ; i += 256) { float e = expf(sc[i] - m); sc[i] = e; sum += e; }
    red[tid] = sum; __syncthreads();
    for (int o = 128; o; o >>= 1) { if (tid < o) red[tid] += red[tid + o]; __syncthreads(); }
    float inv = 1.0f / red[0];
    for (int i = tid; i < SEQ; i += 256) row0_buf[bh * SEQ + i] = sc[i] * inv;
}

// ---------------- conv1d(k=3, 16->1024) + bias + relu ----------------
__global__ __launch_bounds__(256) void conv_kernel(const float* __restrict__ conv_w,
                                                   const float* __restrict__ conv_b,
                                                   float* __restrict__ out)
{
    int b  = blockIdx.z;
    int o0 = blockIdx.y * 64;
    int s0 = blockIdx.x * 512;

    __shared__ float ws[64 * 48];
    __shared__ float bs[64];
    int tid = threadIdx.x;
    for (int idx = tid; idx < 64 * 48; idx += 256)
        ws[idx] = conv_w[o0 * 48 + idx];
    if (tid < 64) bs[tid] = conv_b[o0 + tid];
    __syncthreads();

    int s = s0 + tid * 2;                 // s in [0, 1022], even

    float r[16][4];
    #pragma unroll
    for (int i = 0; i < 16; i++) {
        const float* rp = row0_buf + (b * HEADS + i) * SEQ;
        r[i][0] = (s == 0) ? 0.f : rp[s - 1];
        r[i][1] = rp[s];
        r[i][2] = rp[s + 1];
        r[i][3] = (s + 2 > SEQ - 1) ? 0.f : rp[s + 2];
    }

    for (int o = 0; o < 64; o++) {
        float a0 = bs[o], a1 = bs[o];
        const float* w = &ws[o * 48];
        #pragma unroll
        for (int i = 0; i < 16; i++) {
            float w0 = w[i * 3], w1 = w[i * 3 + 1], w2 = w[i * 3 + 2];
            a0 += r[i][0] * w0 + r[i][1] * w1 + r[i][2] * w2;
            a1 += r[i][1] * w0 + r[i][2] * w1 + r[i][3] * w2;
        }
        float2 v = make_float2(fmaxf(a0, 0.f), fmaxf(a1, 0.f));
        *(float2*)&out[((b * DIM) + (o0 + o)) * SEQ + s] = v;
    }
}

// ---------------- launch ----------------
extern "C" void kernel_launch(void* const* d_in, const int* in_sizes, int n_in,
                              void* d_out, int out_size)
{
    const float* X      = (const float*)d_in[0];
    const int*   mask   = (const int*)  d_in[1];
    const float* W_G    = (const float*)d_in[2];
    const float* b_G    = (const float*)d_in[3];
    const float* Wq     = (const float*)d_in[4];
    const float* bq     = (const float*)d_in[5];
    const float* Wk     = (const float*)d_in[6];
    const float* bk     = (const float*)d_in[7];
    const float* conv_w = (const float*)d_in[8];
    const float* conv_b = (const float*)d_in[9];
    float* out = (float*)d_out;

    rope_tables_kernel<<<SEQ, 32>>>();
    sgemm_kernel<0><<<dim3(DIM / 128, MROWS / 128), 256>>>(X, W_G, b_G);       // g (+g0)
    sgemm_kernel<1><<<dim3(DIM / 128, MROWS / 128), 256>>>(nullptr, Wk, bk);   // kw (+RoPE)
    q0_part_kernel<<<dim3(DIM / 256, 8, BATCH), 256>>>(Wq);
    q0_reduce_kernel<<<BATCH * DIM / 256, 256>>>(bq);
    scores_kernel<<<dim3(SEQ / 128, BATCH * HEADS), 256>>>(mask);
    softmax_kernel<<<BATCH * HEADS, 256>>>();
    conv_kernel<<<dim3(SEQ / 512, DIM / 64, BATCH), 256>>>(conv_w, conv_b, out);
}

// round 7
// speedup vs baseline: 2.0649x; 1.8913x over previous
#include <cuda_runtime.h>
#include <cuda_bf16.h>
#include <math.h>
#include <stdint.h>

// Problem: B=4, S=1024, D=1024, H=16, DK=64
#define SEQ   1024
#define BATCH 4
#define DIM   1024
#define HEADS 16
#define DKH   64
#define MROWS (BATCH * SEQ)   // 4096

__device__ __forceinline__ uint32_t pk_bf16(__nv_bfloat16 a, __nv_bfloat16 b) {
    return (uint32_t)__bfloat16_as_ushort(a) | ((uint32_t)__bfloat16_as_ushort(b) << 16);
}
__device__ __forceinline__ void mma_bf16(float* d, const uint32_t* a, const uint32_t* b) {
    asm volatile("mma.sync.aligned.m16n8k16.row.col.f32.bf16.bf16.f32 "
        "{%0,%1,%2,%3}, {%4,%5,%6,%7}, {%8,%9}, {%0,%1,%2,%3};"
        : "+f"(d[0]), "+f"(d[1]), "+f"(d[2]), "+f"(d[3])
        : "r"(a[0]), "r"(a[1]), "r"(a[2]), "r"(a[3]), "r"(b[0]), "r"(b[1]));
}

// ================= scratch (all referenced ONLY inside device code) =================
__device__ __align__(256) __nv_bfloat16 Xh_buf[MROWS * DIM];
__device__ __align__(256) __nv_bfloat16 Xl_buf[MROWS * DIM];
__device__ __align__(256) __nv_bfloat16 gh_buf[MROWS * DIM];
__device__ __align__(256) __nv_bfloat16 gl_buf[MROWS * DIM];
__device__ __align__(256) __nv_bfloat16 WGt_h[DIM * DIM];
__device__ __align__(256) __nv_bfloat16 WGt_l[DIM * DIM];
__device__ __align__(256) __nv_bfloat16 Wkt_h[DIM * DIM];
__device__ __align__(256) __nv_bfloat16 Wkt_l[DIM * DIM];
__device__ __align__(256) float kw_buf[MROWS * DIM];
__device__ __align__(256) float g0_buf[BATCH * DIM];
__device__ __align__(256) float q0_part[8 * BATCH * DIM];
__device__ __align__(256) float q0_buf[BATCH * DIM];
__device__ __align__(256) float sc_buf[BATCH * HEADS * SEQ];
__device__ __align__(256) float row0_buf[BATCH * HEADS * SEQ];
__device__ __align__(256) float cos_tab[SEQ * 32];
__device__ __align__(256) float sin_tab[SEQ * 32];

// ================= RoPE tables =================
__global__ void rope_tables_kernel() {
    int s = blockIdx.x;
    int j = threadIdx.x;                 // 0..31
    float inv = powf(10000.0f, -((float)j) / 32.0f);
    float ang = (float)s * inv;
    cos_tab[s * 32 + j] = cosf(ang);
    sin_tab[s * 32 + j] = sinf(ang);
}

// ============ weight transpose + hi/lo split:  Wt[n][k] = split(W[k][n]) ============
// WHICH=0 -> WGt_h/WGt_l ; WHICH=1 -> Wkt_h/Wkt_l  (symbols referenced in-body)
template <int WHICH>
__global__ __launch_bounds__(256) void convW_kernel(const float* __restrict__ W)
{
    __nv_bfloat16* Th = (WHICH == 0) ? WGt_h : Wkt_h;
    __nv_bfloat16* Tl = (WHICH == 0) ? WGt_l : Wkt_l;
    __shared__ float tile[32][33];
    int tx = threadIdx.x, ty = threadIdx.y;      // block (32, 8)
    int k0 = blockIdx.y * 32, n0 = blockIdx.x * 32;
    #pragma unroll
    for (int j = 0; j < 32; j += 8)
        tile[ty + j][tx] = W[(size_t)(k0 + ty + j) * DIM + n0 + tx];
    __syncthreads();
    #pragma unroll
    for (int j = 0; j < 32; j += 8) {
        float v = tile[tx][ty + j];
        __nv_bfloat16 h = __float2bfloat16(v);
        __nv_bfloat16 l = __float2bfloat16(v - __bfloat162float(h));
        size_t o = (size_t)(n0 + ty + j) * DIM + k0 + tx;
        Th[o] = h; Tl[o] = l;
    }
}

// ============ X hi/lo split (elementwise) ============
__global__ __launch_bounds__(256) void convX_kernel(const float* __restrict__ X)
{
    int idx = blockIdx.x * 256 + threadIdx.x;    // over MROWS*DIM/4
    float4 v = ((const float4*)X)[idx];
    __nv_bfloat16 h0 = __float2bfloat16(v.x), h1 = __float2bfloat16(v.y);
    __nv_bfloat16 h2 = __float2bfloat16(v.z), h3 = __float2bfloat16(v.w);
    __nv_bfloat16 l0 = __float2bfloat16(v.x - __bfloat162float(h0));
    __nv_bfloat16 l1 = __float2bfloat16(v.y - __bfloat162float(h1));
    __nv_bfloat16 l2 = __float2bfloat16(v.z - __bfloat162float(h2));
    __nv_bfloat16 l3 = __float2bfloat16(v.w - __bfloat162float(h3));
    ((uint2*)Xh_buf)[idx] = make_uint2(pk_bf16(h0, h1), pk_bf16(h2, h3));
    ((uint2*)Xl_buf)[idx] = make_uint2(pk_bf16(l0, l1), pk_bf16(l2, l3));
}

// ================= mma.sync split-bf16 GEMM =================
// C[4096,1024] = (Ah+Al) x (Bh+Bl)^T  (B stored [N][K] K-major), fp32 accum.
// 3 passes into one accumulator: Ah*Bh + Al*Bh + Ah*Bl.
// CTA tile 128x128, k-tile 32. Static 40KB smem, sync loads, 2 CTAs/SM.
// PHASE 0: X(h/l) x WGt -> +bias -> gh/gl (+ g0 at s==0). PHASE 1: g(h/l) x Wkt -> +bias,RoPE -> kw.
#define WPITCH 20

template <int PHASE>
__global__ __launch_bounds__(256, 2) void gemm_kernel(const float* __restrict__ bias)
{
    __shared__ __align__(16) uint32_t s32[10240];   // 4 tensors x 128 rows x 20 words
    const int tid = threadIdx.x;
    const int wid = tid >> 5, lane = tid & 31;
    const int gID = lane >> 2, tig = lane & 3;
    const int m0 = blockIdx.y * 128, n0 = blockIdx.x * 128;
    const int wm = (wid & 3) * 32, wn = (wid >> 2) * 64;

    uint32_t* const sAh = s32;
    uint32_t* const sAl = s32 + 2560;
    uint32_t* const sBh = s32 + 5120;
    uint32_t* const sBl = s32 + 7680;

    const __nv_bfloat16* gptr[4];
    if (PHASE == 0) {
        gptr[0] = Xh_buf + (size_t)m0 * DIM;  gptr[1] = Xl_buf + (size_t)m0 * DIM;
        gptr[2] = WGt_h  + (size_t)n0 * DIM;  gptr[3] = WGt_l  + (size_t)n0 * DIM;
    } else {
        gptr[0] = gh_buf + (size_t)m0 * DIM;  gptr[1] = gl_buf + (size_t)m0 * DIM;
        gptr[2] = Wkt_h  + (size_t)n0 * DIM;  gptr[3] = Wkt_l  + (size_t)n0 * DIM;
    }

    float acc[2][8][4] = {};

    // this thread's 8 copy slots (2048 uint4 total): cid -> (tensor, row, 16B chunk)
    int c_ten[8], c_row[8], c_ch[8];
    #pragma unroll
    for (int p = 0; p < 8; p++) {
        int cid = p * 256 + tid;
        c_ten[p] = cid >> 9;
        int rc = cid & 511;
        c_row[p] = rc >> 2;
        c_ch[p]  = rc & 3;
    }

    for (int t = 0; t < 32; t++) {
        const int k0 = t * 32;
        __syncthreads();
        #pragma unroll
        for (int half = 0; half < 2; half++) {
            uint4 v[4];
            #pragma unroll
            for (int q = 0; q < 4; q++) {
                int p = half * 4 + q;
                v[q] = *(const uint4*)(gptr[c_ten[p]] + (size_t)c_row[p] * DIM + k0 + c_ch[p] * 8);
            }
            #pragma unroll
            for (int q = 0; q < 4; q++) {
                int p = half * 4 + q;
                *(uint4*)((char*)s32 + c_ten[p] * 10240 + c_row[p] * 80 + c_ch[p] * 16) = v[q];
            }
        }
        __syncthreads();

        #pragma unroll
        for (int kb = 0; kb < 2; kb++) {
            const int kwd = kb * 8 + tig;      // word offset within row for this k-step
            uint32_t afh[2][4], afl[2][4];
            #pragma unroll
            for (int mi = 0; mi < 2; mi++) {
                int r = wm + mi * 16 + gID;
                afh[mi][0] = sAh[r * WPITCH + kwd];
                afh[mi][1] = sAh[(r + 8) * WPITCH + kwd];
                afh[mi][2] = sAh[r * WPITCH + kwd + 4];
                afh[mi][3] = sAh[(r + 8) * WPITCH + kwd + 4];
                afl[mi][0] = sAl[r * WPITCH + kwd];
                afl[mi][1] = sAl[(r + 8) * WPITCH + kwd];
                afl[mi][2] = sAl[r * WPITCH + kwd + 4];
                afl[mi][3] = sAl[(r + 8) * WPITCH + kwd + 4];
            }
            #pragma unroll
            for (int nj = 0; nj < 4; nj++) {
                #pragma unroll
                for (int hf = 0; hf < 2; hf++) {
                    int rn = wn + nj * 16 + hf * 8 + gID;
                    uint32_t bh2[2], bl2[2];
                    bh2[0] = sBh[rn * WPITCH + kwd];
                    bh2[1] = sBh[rn * WPITCH + kwd + 4];
                    bl2[0] = sBl[rn * WPITCH + kwd];
                    bl2[1] = sBl[rn * WPITCH + kwd + 4];
                    #pragma unroll
                    for (int mi = 0; mi < 2; mi++) {
                        mma_bf16(acc[mi][nj * 2 + hf], afh[mi], bh2);
                        mma_bf16(acc[mi][nj * 2 + hf], afl[mi], bh2);
                        mma_bf16(acc[mi][nj * 2 + hf], afh[mi], bl2);
                    }
                }
            }
        }
    }

    // ---- epilogue: acc[mi][j][*] covers rows wm+mi*16+gID(+8), cols wn+j*8+tig*2(,+1)
    #pragma unroll
    for (int mi = 0; mi < 2; mi++) {
        #pragma unroll
        for (int j = 0; j < 8; j++) {
            int n = n0 + wn + j * 8 + tig * 2;
            #pragma unroll
            for (int hh = 0; hh < 2; hh++) {
                int row = m0 + wm + mi * 16 + gID + hh * 8;
                float v0 = acc[mi][j][hh * 2]     + bias[n];
                float v1 = acc[mi][j][hh * 2 + 1] + bias[n + 1];
                if (PHASE == 0) {
                    __nv_bfloat16 h0 = __float2bfloat16(v0), h1 = __float2bfloat16(v1);
                    __nv_bfloat16 l0 = __float2bfloat16(v0 - __bfloat162float(h0));
                    __nv_bfloat16 l1 = __float2bfloat16(v1 - __bfloat162float(h1));
                    *(uint32_t*)&gh_buf[(size_t)row * DIM + n] = pk_bf16(h0, h1);
                    *(uint32_t*)&gl_buf[(size_t)row * DIM + n] = pk_bf16(l0, l1);
                    if ((row & (SEQ - 1)) == 0) {
                        g0_buf[(row >> 10) * DIM + n]     = v0;
                        g0_buf[(row >> 10) * DIM + n + 1] = v1;
                    }
                } else {
                    int s = row & (SEQ - 1);
                    int jj = (n & (DKH - 1)) >> 1;
                    float cs = cos_tab[s * 32 + jj];
                    float sn = sin_tab[s * 32 + jj];
                    *(float2*)&kw_buf[(size_t)row * DIM + n] =
                        make_float2(v0 * cs - v1 * sn, v1 * cs + v0 * sn);
                }
            }
        }
    }
}

// ============ q0 = g0 @ Wq (split-K partials), fp32 ============
__global__ __launch_bounds__(256) void q0_part_kernel(const float* __restrict__ Wq)
{
    __shared__ float gs[128];
    int b = blockIdx.z, ks = blockIdx.y, cb = blockIdx.x;
    int col = cb * 256 + threadIdx.x;
    if (threadIdx.x < 128) gs[threadIdx.x] = g0_buf[b * DIM + ks * 128 + threadIdx.x];
    __syncthreads();
    float a = 0.f;
    #pragma unroll 8
    for (int i = 0; i < 128; i++)
        a += gs[i] * Wq[(size_t)(ks * 128 + i) * DIM + col];
    q0_part[(ks * BATCH + b) * DIM + col] = a;
}
__global__ __launch_bounds__(256) void q0_reduce_kernel(const float* __restrict__ bq)
{
    int idx = blockIdx.x * 256 + threadIdx.x;    // 0..4095
    int b = idx >> 10, col = idx & (DIM - 1);
    float a = bq[col];
    #pragma unroll
    for (int ks = 0; ks < 8; ks++) a += q0_part[(ks * BATCH + b) * DIM + col];
    q0_buf[idx] = a;
}

// ============ scores (parallel over 512 CTAs) ============
__global__ __launch_bounds__(256) void scores_kernel(const int* __restrict__ mask)
{
    int bh = blockIdx.y, seg = blockIdx.x;
    int b = bh >> 4, h = bh & 15;
    __shared__ float q0s[DKH];
    int tid = threadIdx.x;
    if (tid < DKH) q0s[tid] = q0_buf[b * DIM + h * DKH + tid];
    __syncthreads();
    int lane = tid & 31, warp = tid >> 5;
    #pragma unroll 4
    for (int i = 0; i < 16; i++) {
        int s = seg * 128 + i * 8 + warp;
        const float* kr = kw_buf + ((size_t)(b * SEQ + s)) * DIM + h * DKH;
        float v = q0s[lane] * kr[lane] + q0s[lane + 32] * kr[lane + 32];
        #pragma unroll
        for (int o = 16; o; o >>= 1) v += __shfl_down_sync(0xffffffffu, v, o);
        if (lane == 0) {
            float sv = v * 0.125f;   // 1/sqrt(64)
            if (mask[b * SEQ + s] == 0) sv = -1e9f;
            sc_buf[bh * SEQ + s] = sv;
        }
    }
}

// ============ softmax over 1024 ============
__global__ __launch_bounds__(256) void softmax_kernel()
{
    int bh = blockIdx.x;
    __shared__ float sc[SEQ];
    __shared__ float red[256];
    int tid = threadIdx.x;
    float m = -1e30f;
    for (int i = tid; i < SEQ; i += 256) { float v = sc_buf[bh * SEQ + i]; sc[i] = v; m = fmaxf(m, v); }
    red[tid] = m; __syncthreads();
    for (int o = 128; o; o >>= 1) { if (tid < o) red[tid] = fmaxf(red[tid], red[tid + o]); __syncthreads(); }
    m = red[0]; __syncthreads();
    float sum = 0.f;
    for (int i = tid; i < SEQ; i += 256) { float e = expf(sc[i] - m); sc[i] = e; sum += e; }
    red[tid] = sum; __syncthreads();
    for (int o = 128; o; o >>= 1) { if (tid < o) red[tid] += red[tid + o]; __syncthreads(); }
    float inv = 1.0f / red[0];
    for (int i = tid; i < SEQ; i += 256) row0_buf[bh * SEQ + i] = sc[i] * inv;
}

// ============ conv1d(k=3, 16->1024) + bias + relu ============
__global__ __launch_bounds__(256) void conv_kernel(const float* __restrict__ conv_w,
                                                   const float* __restrict__ conv_b,
                                                   float* __restrict__ out)
{
    int b  = blockIdx.z;
    int o0 = blockIdx.y * 64;
    int s0 = blockIdx.x * 512;
    __shared__ float ws[64 * 48];
    __shared__ float bs[64];
    int tid = threadIdx.x;
    for (int idx = tid; idx < 64 * 48; idx += 256) ws[idx] = conv_w[o0 * 48 + idx];
    if (tid < 64) bs[tid] = conv_b[o0 + tid];
    __syncthreads();
    int s = s0 + tid * 2;
    float r[16][4];
    #pragma unroll
    for (int i = 0; i < 16; i++) {
        const float* rp = row0_buf + (b * HEADS + i) * SEQ;
        r[i][0] = (s == 0) ? 0.f : rp[s - 1];
        r[i][1] = rp[s];
        r[i][2] = rp[s + 1];
        r[i][3] = (s + 2 > SEQ - 1) ? 0.f : rp[s + 2];
    }
    for (int o = 0; o < 64; o++) {
        float a0 = bs[o], a1 = bs[o];
        const float* w = &ws[o * 48];
        #pragma unroll
        for (int i = 0; i < 16; i++) {
            float w0 = w[i*3], w1 = w[i*3+1], w2 = w[i*3+2];
            a0 += r[i][0]*w0 + r[i][1]*w1 + r[i][2]*w2;
            a1 += r[i][1]*w0 + r[i][2]*w1 + r[i][3]*w2;
        }
        *(float2*)&out[((size_t)(b * DIM) + (o0 + o)) * SEQ + s] =
            make_float2(fmaxf(a0, 0.f), fmaxf(a1, 0.f));
    }
}

// ================= launch =================
extern "C" void kernel_launch(void* const* d_in, const int* in_sizes, int n_in,
                              void* d_out, int out_size)
{
    const float* X      = (const float*)d_in[0];
    const int*   mask   = (const int*)  d_in[1];
    const float* W_G    = (const float*)d_in[2];
    const float* b_G    = (const float*)d_in[3];
    const float* Wq     = (const float*)d_in[4];
    const float* bq     = (const float*)d_in[5];
    const float* Wk     = (const float*)d_in[6];
    const float* bk     = (const float*)d_in[7];
    const float* conv_w = (const float*)d_in[8];
    const float* conv_b = (const float*)d_in[9];
    float* out = (float*)d_out;

    rope_tables_kernel<<<SEQ, 32>>>();
    convW_kernel<0><<<dim3(DIM/32, DIM/32), dim3(32, 8)>>>(W_G);
    convW_kernel<1><<<dim3(DIM/32, DIM/32), dim3(32, 8)>>>(Wk);
    convX_kernel<<<MROWS * DIM / 4 / 256, 256>>>(X);

    gemm_kernel<0><<<dim3(DIM/128, MROWS/128), 256>>>(b_G);
    gemm_kernel<1><<<dim3(DIM/128, MROWS/128), 256>>>(bk);

    q0_part_kernel<<<dim3(DIM/256, 8, BATCH), 256>>>(Wq);
    q0_reduce_kernel<<<BATCH * DIM / 256, 256>>>(bq);
    scores_kernel<<<dim3(SEQ/128, BATCH*HEADS), 256>>>(mask);
    softmax_kernel<<<BATCH * HEADS, 256>>>();
    conv_kernel<<<dim3(SEQ/512, DIM/64, BATCH), 256>>>(conv_w, conv_b, out);
}

// round 8
// speedup vs baseline: 2.3285x; 1.1277x over previous
#include <cuda_runtime.h>
#include <cuda_bf16.h>
#include <math.h>
#include <stdint.h>

// Problem: B=4, S=1024, D=1024, H=16, DK=64
#define SEQ   1024
#define BATCH 4
#define DIM   1024
#define HEADS 16
#define DKH   64
#define MROWS (BATCH * SEQ)   // 4096

__device__ __forceinline__ uint32_t smem_to_u32(const void* p) {
    uint32_t a;
    asm("{ .reg .u64 t; cvta.to.shared.u64 t, %1; cvt.u32.u64 %0, t; }" : "=r"(a) : "l"(p));
    return a;
}
__device__ __forceinline__ uint32_t pk_bf16(__nv_bfloat16 a, __nv_bfloat16 b) {
    return (uint32_t)__bfloat16_as_ushort(a) | ((uint32_t)__bfloat16_as_ushort(b) << 16);
}
__device__ __forceinline__ void mma_bf16(float* d, const uint32_t* a, const uint32_t* b) {
    asm volatile("mma.sync.aligned.m16n8k16.row.col.f32.bf16.bf16.f32 "
        "{%0,%1,%2,%3}, {%4,%5,%6,%7}, {%8,%9}, {%0,%1,%2,%3};"
        : "+f"(d[0]), "+f"(d[1]), "+f"(d[2]), "+f"(d[3])
        : "r"(a[0]), "r"(a[1]), "r"(a[2]), "r"(a[3]), "r"(b[0]), "r"(b[1]));
}
#define CP_ASYNC16(saddr, gaddr) \
    asm volatile("cp.async.cg.shared.global [%0], [%1], 16;" :: "r"(saddr), "l"(gaddr) : "memory")
#define CP_COMMIT() asm volatile("cp.async.commit_group;" ::: "memory")
#define CP_WAIT0()  asm volatile("cp.async.wait_group 0;" ::: "memory")

// ================= scratch (referenced ONLY inside device code) =================
__device__ __align__(256) __nv_bfloat16 Xh_buf[MROWS * DIM];
__device__ __align__(256) __nv_bfloat16 Xl_buf[MROWS * DIM];
__device__ __align__(256) __nv_bfloat16 gh_buf[MROWS * DIM];
__device__ __align__(256) __nv_bfloat16 gl_buf[MROWS * DIM];
__device__ __align__(256) __nv_bfloat16 WGt_h[DIM * DIM];
__device__ __align__(256) __nv_bfloat16 WGt_l[DIM * DIM];
__device__ __align__(256) __nv_bfloat16 Wkt_h[DIM * DIM];
__device__ __align__(256) __nv_bfloat16 Wkt_l[DIM * DIM];
__device__ __align__(256) float kw_buf[MROWS * DIM];
__device__ __align__(256) float g0_buf[BATCH * DIM];
__device__ __align__(256) float q0_part[32 * BATCH * DIM];
__device__ __align__(256) float q0_buf[BATCH * DIM];
__device__ __align__(256) float sc_buf[BATCH * HEADS * SEQ];
__device__ __align__(256) float row0_buf[BATCH * HEADS * SEQ];
__device__ __align__(256) float cos_tab[SEQ * 32];
__device__ __align__(256) float sin_tab[SEQ * 32];

// ================= RoPE tables =================
__global__ void rope_tables_kernel() {
    int s = blockIdx.x;
    int j = threadIdx.x;                 // 0..31
    float inv = powf(10000.0f, -((float)j) / 32.0f);
    float ang = (float)s * inv;
    cos_tab[s * 32 + j] = cosf(ang);
    sin_tab[s * 32 + j] = sinf(ang);
}

// ============ weight transpose + hi/lo split:  Wt[n][k] = split(W[k][n]) ============
template <int WHICH>
__global__ __launch_bounds__(256) void convW_kernel(const float* __restrict__ W)
{
    __nv_bfloat16* Th = (WHICH == 0) ? WGt_h : Wkt_h;
    __nv_bfloat16* Tl = (WHICH == 0) ? WGt_l : Wkt_l;
    __shared__ float tile[32][33];
    int tx = threadIdx.x, ty = threadIdx.y;      // block (32, 8)
    int k0 = blockIdx.y * 32, n0 = blockIdx.x * 32;
    #pragma unroll
    for (int j = 0; j < 32; j += 8)
        tile[ty + j][tx] = W[(size_t)(k0 + ty + j) * DIM + n0 + tx];
    __syncthreads();
    #pragma unroll
    for (int j = 0; j < 32; j += 8) {
        float v = tile[tx][ty + j];
        __nv_bfloat16 h = __float2bfloat16(v);
        __nv_bfloat16 l = __float2bfloat16(v - __bfloat162float(h));
        size_t o = (size_t)(n0 + ty + j) * DIM + k0 + tx;
        Th[o] = h; Tl[o] = l;
    }
}

// ============ X hi/lo split (elementwise) ============
__global__ __launch_bounds__(256) void convX_kernel(const float* __restrict__ X)
{
    int idx = blockIdx.x * 256 + threadIdx.x;    // over MROWS*DIM/4
    float4 v = ((const float4*)X)[idx];
    __nv_bfloat16 h0 = __float2bfloat16(v.x), h1 = __float2bfloat16(v.y);
    __nv_bfloat16 h2 = __float2bfloat16(v.z), h3 = __float2bfloat16(v.w);
    __nv_bfloat16 l0 = __float2bfloat16(v.x - __bfloat162float(h0));
    __nv_bfloat16 l1 = __float2bfloat16(v.y - __bfloat162float(h1));
    __nv_bfloat16 l2 = __float2bfloat16(v.z - __bfloat162float(h2));
    __nv_bfloat16 l3 = __float2bfloat16(v.w - __bfloat162float(h3));
    ((uint2*)Xh_buf)[idx] = make_uint2(pk_bf16(h0, h1), pk_bf16(h2, h3));
    ((uint2*)Xl_buf)[idx] = make_uint2(pk_bf16(l0, l1), pk_bf16(l2, l3));
}

// ================= mma.sync split-bf16 GEMM, cp.async 2-stage pipeline =================
// C[4096,1024] = (Ah+Al) x (Bh+Bl)^T  (B stored [N][K] K-major), fp32 accum.
// 3 passes into one accumulator: Ah*Bh + Al*Bh + Ah*Bl.
// CTA tile 128x128, k-tile 32. Dynamic smem 80KB (2 stages x 40KB), 2 CTAs/SM.
#define WPITCH 20
#define STAGE_WORDS 10240     // 40KB per stage

template <int PHASE>
__global__ __launch_bounds__(256, 2) void gemm_kernel(const float* __restrict__ bias)
{
    extern __shared__ __align__(16) uint32_t s32[];     // 2 x 10240 words
    const uint32_t sbu = smem_to_u32(s32);
    const int tid = threadIdx.x;
    const int wid = tid >> 5, lane = tid & 31;
    const int gID = lane >> 2, tig = lane & 3;
    const int m0 = blockIdx.y * 128, n0 = blockIdx.x * 128;
    const int wm = (wid & 3) * 32, wn = (wid >> 2) * 64;

    const __nv_bfloat16* gptr[4];
    if (PHASE == 0) {
        gptr[0] = Xh_buf + (size_t)m0 * DIM;  gptr[1] = Xl_buf + (size_t)m0 * DIM;
        gptr[2] = WGt_h  + (size_t)n0 * DIM;  gptr[3] = WGt_l  + (size_t)n0 * DIM;
    } else {
        gptr[0] = gh_buf + (size_t)m0 * DIM;  gptr[1] = gl_buf + (size_t)m0 * DIM;
        gptr[2] = Wkt_h  + (size_t)n0 * DIM;  gptr[3] = Wkt_l  + (size_t)n0 * DIM;
    }

    // this thread's 8 copy slots (2048 x 16B per stage): cid -> (tensor, row, chunk)
    int c_ten[8], c_row[8], c_ch[8];
    #pragma unroll
    for (int p = 0; p < 8; p++) {
        int cid = p * 256 + tid;
        c_ten[p] = cid >> 9;
        int rc = cid & 511;
        c_row[p] = rc >> 2;
        c_ch[p]  = rc & 3;
    }

    auto load_stage = [&](int buf, int t) {
        const int k0 = t * 32;
        #pragma unroll
        for (int p = 0; p < 8; p++) {
            uint32_t sa = sbu + (buf * STAGE_WORDS + c_ten[p] * 2560) * 4
                              + c_row[p] * 80 + c_ch[p] * 16;
            CP_ASYNC16(sa, gptr[c_ten[p]] + (size_t)c_row[p] * DIM + k0 + c_ch[p] * 8);
        }
    };

    float acc[2][8][4] = {};

    load_stage(0, 0); CP_COMMIT();

    for (int t = 0; t < 32; t++) {
        CP_WAIT0();
        __syncthreads();
        if (t + 1 < 32) { load_stage((t + 1) & 1, t + 1); CP_COMMIT(); }

        uint32_t* const sAh = s32 + (t & 1) * STAGE_WORDS;
        uint32_t* const sAl = sAh + 2560;
        uint32_t* const sBh = sAh + 5120;
        uint32_t* const sBl = sAh + 7680;

        #pragma unroll
        for (int kb = 0; kb < 2; kb++) {
            const int kwd = kb * 8 + tig;
            uint32_t afh[2][4], afl[2][4];
            #pragma unroll
            for (int mi = 0; mi < 2; mi++) {
                int r = wm + mi * 16 + gID;
                afh[mi][0] = sAh[r * WPITCH + kwd];
                afh[mi][1] = sAh[(r + 8) * WPITCH + kwd];
                afh[mi][2] = sAh[r * WPITCH + kwd + 4];
                afh[mi][3] = sAh[(r + 8) * WPITCH + kwd + 4];
                afl[mi][0] = sAl[r * WPITCH + kwd];
                afl[mi][1] = sAl[(r + 8) * WPITCH + kwd];
                afl[mi][2] = sAl[r * WPITCH + kwd + 4];
                afl[mi][3] = sAl[(r + 8) * WPITCH + kwd + 4];
            }
            #pragma unroll
            for (int nj = 0; nj < 4; nj++) {
                #pragma unroll
                for (int hf = 0; hf < 2; hf++) {
                    int rn = wn + nj * 16 + hf * 8 + gID;
                    uint32_t bh2[2], bl2[2];
                    bh2[0] = sBh[rn * WPITCH + kwd];
                    bh2[1] = sBh[rn * WPITCH + kwd + 4];
                    bl2[0] = sBl[rn * WPITCH + kwd];
                    bl2[1] = sBl[rn * WPITCH + kwd + 4];
                    #pragma unroll
                    for (int mi = 0; mi < 2; mi++) {
                        mma_bf16(acc[mi][nj * 2 + hf], afh[mi], bh2);
                        mma_bf16(acc[mi][nj * 2 + hf], afl[mi], bh2);
                        mma_bf16(acc[mi][nj * 2 + hf], afh[mi], bl2);
                    }
                }
            }
        }
    }

    // ---- epilogue: acc[mi][j][*] -> rows wm+mi*16+gID(+8), cols wn+j*8+tig*2(,+1)
    #pragma unroll
    for (int mi = 0; mi < 2; mi++) {
        #pragma unroll
        for (int j = 0; j < 8; j++) {
            int n = n0 + wn + j * 8 + tig * 2;
            #pragma unroll
            for (int hh = 0; hh < 2; hh++) {
                int row = m0 + wm + mi * 16 + gID + hh * 8;
                float v0 = acc[mi][j][hh * 2]     + bias[n];
                float v1 = acc[mi][j][hh * 2 + 1] + bias[n + 1];
                if (PHASE == 0) {
                    __nv_bfloat16 h0 = __float2bfloat16(v0), h1 = __float2bfloat16(v1);
                    __nv_bfloat16 l0 = __float2bfloat16(v0 - __bfloat162float(h0));
                    __nv_bfloat16 l1 = __float2bfloat16(v1 - __bfloat162float(h1));
                    *(uint32_t*)&gh_buf[(size_t)row * DIM + n] = pk_bf16(h0, h1);
                    *(uint32_t*)&gl_buf[(size_t)row * DIM + n] = pk_bf16(l0, l1);
                    if ((row & (SEQ - 1)) == 0) {
                        g0_buf[(row >> 10) * DIM + n]     = v0;
                        g0_buf[(row >> 10) * DIM + n + 1] = v1;
                    }
                } else {
                    int s = row & (SEQ - 1);
                    int jj = (n & (DKH - 1)) >> 1;
                    float cs = cos_tab[s * 32 + jj];
                    float sn = sin_tab[s * 32 + jj];
                    *(float2*)&kw_buf[(size_t)row * DIM + n] =
                        make_float2(v0 * cs - v1 * sn, v1 * cs + v0 * sn);
                }
            }
        }
    }
}

// ============ q0 = g0 @ Wq (split-K x32 partials), fp32 ============
__global__ __launch_bounds__(256) void q0_part_kernel(const float* __restrict__ Wq)
{
    __shared__ float gs[32];
    int b = blockIdx.z, ks = blockIdx.y, cb = blockIdx.x;
    int col = cb * 256 + threadIdx.x;
    if (threadIdx.x < 32) gs[threadIdx.x] = g0_buf[b * DIM + ks * 32 + threadIdx.x];
    __syncthreads();
    float a = 0.f;
    #pragma unroll
    for (int i = 0; i < 32; i++)
        a += gs[i] * Wq[(size_t)(ks * 32 + i) * DIM + col];
    q0_part[(ks * BATCH + b) * DIM + col] = a;
}
__global__ __launch_bounds__(256) void q0_reduce_kernel(const float* __restrict__ bq)
{
    int idx = blockIdx.x * 256 + threadIdx.x;    // 0..4095
    int b = idx >> 10, col = idx & (DIM - 1);
    float a = bq[col];
    #pragma unroll
    for (int ks = 0; ks < 32; ks++) a += q0_part[(ks * BATCH + b) * DIM + col];
    q0_buf[idx] = a;
}

// ============ scores (parallel over 512 CTAs) ============
__global__ __launch_bounds__(256) void scores_kernel(const int* __restrict__ mask)
{
    int bh = blockIdx.y, seg = blockIdx.x;
    int b = bh >> 4, h = bh & 15;
    __shared__ float q0s[DKH];
    int tid = threadIdx.x;
    if (tid < DKH) q0s[tid] = q0_buf[b * DIM + h * DKH + tid];
    __syncthreads();
    int lane = tid & 31, warp = tid >> 5;
    #pragma unroll 4
    for (int i = 0; i < 16; i++) {
        int s = seg * 128 + i * 8 + warp;
        const float* kr = kw_buf + ((size_t)(b * SEQ + s)) * DIM + h * DKH;
        float v = q0s[lane] * kr[lane] + q0s[lane + 32] * kr[lane + 32];
        #pragma unroll
        for (int o = 16; o; o >>= 1) v += __shfl_down_sync(0xffffffffu, v, o);
        if (lane == 0) {
            float sv = v * 0.125f;   // 1/sqrt(64)
            if (mask[b * SEQ + s] == 0) sv = -1e9f;
            sc_buf[bh * SEQ + s] = sv;
        }
    }
}

// ============ softmax over 1024 ============
__global__ __launch_bounds__(256) void softmax_kernel()
{
    int bh = blockIdx.x;
    __shared__ float sc[SEQ];
    __shared__ float red[256];
    int tid = threadIdx.x;
    float m = -1e30f;
    for (int i = tid; i < SEQ; i += 256) { float v = sc_buf[bh * SEQ + i]; sc[i] = v; m = fmaxf(m, v); }
    red[tid] = m; __syncthreads();
    for (int o = 128; o; o >>= 1) { if (tid < o) red[tid] = fmaxf(red[tid], red[tid + o]); __syncthreads(); }
    m = red[0]; __syncthreads();
    float sum = 0.f;
    for (int i = tid; i < SEQ; i += 256) { float e = expf(sc[i] - m); sc[i] = e; sum += e; }
    red[tid] = sum; __syncthreads();
    for (int o = 128; o; o >>= 1) { if (tid < o) red[tid] += red[tid + o]; __syncthreads(); }
    float inv = 1.0f / red[0];
    for (int i = tid; i < SEQ; i += 256) row0_buf[bh * SEQ + i] = sc[i] * inv;
}

// ============ conv1d(k=3, 16->1024) + bias + relu ============
__global__ __launch_bounds__(256) void conv_kernel(const float* __restrict__ conv_w,
                                                   const float* __restrict__ conv_b,
                                                   float* __restrict__ out)
{
    int b  = blockIdx.z;
    int o0 = blockIdx.y * 64;
    int s0 = blockIdx.x * 512;
    __shared__ float ws[64 * 48];
    __shared__ float bs[64];
    int tid = threadIdx.x;
    for (int idx = tid; idx < 64 * 48; idx += 256) ws[idx] = conv_w[o0 * 48 + idx];
    if (tid < 64) bs[tid] = conv_b[o0 + tid];
    __syncthreads();
    int s = s0 + tid * 2;
    float r[16][4];
    #pragma unroll
    for (int i = 0; i < 16; i++) {
        const float* rp = row0_buf + (b * HEADS + i) * SEQ;
        r[i][0] = (s == 0) ? 0.f : rp[s - 1];
        r[i][1] = rp[s];
        r[i][2] = rp[s + 1];
        r[i][3] = (s + 2 > SEQ - 1) ? 0.f : rp[s + 2];
    }
    for (int o = 0; o < 64; o++) {
        float a0 = bs[o], a1 = bs[o];
        const float* w = &ws[o * 48];
        #pragma unroll
        for (int i = 0; i < 16; i++) {
            float w0 = w[i*3], w1 = w[i*3+1], w2 = w[i*3+2];
            a0 += r[i][0]*w0 + r[i][1]*w1 + r[i][2]*w2;
            a1 += r[i][1]*w0 + r[i][2]*w1 + r[i][3]*w2;
        }
        *(float2*)&out[((size_t)(b * DIM) + (o0 + o)) * SEQ + s] =
            make_float2(fmaxf(a0, 0.f), fmaxf(a1, 0.f));
    }
}

// ================= launch =================
#define GSMEM (2 * STAGE_WORDS * 4)   // 81920 bytes

extern "C" void kernel_launch(void* const* d_in, const int* in_sizes, int n_in,
                              void* d_out, int out_size)
{
    const float* X      = (const float*)d_in[0];
    const int*   mask   = (const int*)  d_in[1];
    const float* W_G    = (const float*)d_in[2];
    const float* b_G    = (const float*)d_in[3];
    const float* Wq     = (const float*)d_in[4];
    const float* bq     = (const float*)d_in[5];
    const float* Wk     = (const float*)d_in[6];
    const float* bk     = (const float*)d_in[7];
    const float* conv_w = (const float*)d_in[8];
    const float* conv_b = (const float*)d_in[9];
    float* out = (float*)d_out;

    cudaFuncSetAttribute(gemm_kernel<0>, cudaFuncAttributeMaxDynamicSharedMemorySize, GSMEM);
    cudaFuncSetAttribute(gemm_kernel<1>, cudaFuncAttributeMaxDynamicSharedMemorySize, GSMEM);

    rope_tables_kernel<<<SEQ, 32>>>();
    convW_kernel<0><<<dim3(DIM/32, DIM/32), dim3(32, 8)>>>(W_G);
    convW_kernel<1><<<dim3(DIM/32, DIM/32), dim3(32, 8)>>>(Wk);
    convX_kernel<<<MROWS * DIM / 4 / 256, 256>>>(X);

    gemm_kernel<0><<<dim3(DIM/128, MROWS/128), 256, GSMEM>>>(b_G);
    gemm_kernel<1><<<dim3(DIM/128, MROWS/128), 256, GSMEM>>>(bk);

    q0_part_kernel<<<dim3(DIM/256, 32, BATCH), 256>>>(Wq);
    q0_reduce_kernel<<<BATCH * DIM / 256, 256>>>(bq);
    scores_kernel<<<dim3(SEQ/128, BATCH*HEADS), 256>>>(mask);
    softmax_kernel<<<BATCH * HEADS, 256>>>();
    conv_kernel<<<dim3(SEQ/512, DIM/64, BATCH), 256>>>(conv_w, conv_b, out);
}